// round 1
// baseline (speedup 1.0000x reference)
#include <cuda_runtime.h>

// Ball query: N1=4096 queries, N2=16384 reference points, K=32, radius=0.08.
// Output (float32, concatenated): mapping [N1*K], num [N1], outputs [N1*K*3].
//
// Distance formula replicates the reference EXACTLY:
//   d2 = (s1 + s2) - 2*dot,  s = ((x*x + y*y) + z*z) via mul/add (no fma),
//   dot = fmaf(z1,z2, fmaf(y1,y2, x1*x2))  (GEMM-style fma accumulation chain)
// Boundary decisions (d2 <= r^2) cascade into index shifts, so formula fidelity
// matters more than raw speed here.

#define BQ_N1 4096
#define BQ_N2 16384
#define BQ_K 32
#define BQ_R2 0.0064f  // 0.08^2

// Scratch: p2 packed as float4 (x, y, z, |p|^2). 256 KB static device array.
__device__ float4 g_bq_p2[BQ_N2];

__global__ void bq_pack_p2(const float* __restrict__ p2) {
    int j = blockIdx.x * blockDim.x + threadIdx.x;
    if (j < BQ_N2) {
        float x = p2[3 * j + 0];
        float y = p2[3 * j + 1];
        float z = p2[3 * j + 2];
        // sum(p*p) with XLA-style mul-then-add (no fma contraction)
        float s2 = __fadd_rn(__fadd_rn(__fmul_rn(x, x), __fmul_rn(y, y)),
                             __fmul_rn(z, z));
        g_bq_p2[j] = make_float4(x, y, z, s2);
    }
}

__global__ __launch_bounds__(256) void bq_query(const float* __restrict__ p1,
                                                float* __restrict__ out) {
    int gwarp = (blockIdx.x * blockDim.x + threadIdx.x) >> 5;
    int lane = threadIdx.x & 31;
    if (gwarp >= BQ_N1) return;

    float x1 = p1[3 * gwarp + 0];
    float y1 = p1[3 * gwarp + 1];
    float z1 = p1[3 * gwarp + 2];
    float s1 = __fadd_rn(__fadd_rn(__fmul_rn(x1, x1), __fmul_rn(y1, y1)),
                         __fmul_rn(z1, z1));

    float* mapping = out + (size_t)gwarp * BQ_K;
    float* num_out = out + (size_t)BQ_N1 * BQ_K + gwarp;
    float* coords  = out + (size_t)BQ_N1 * BQ_K + BQ_N1 + (size_t)gwarp * BQ_K * 3;

    unsigned lanes_below = (1u << lane) - 1u;
    int cnt = 0;

    #pragma unroll 1
    for (int base = 0; base < BQ_N2; base += 32) {
        int j = base + lane;
        float4 q = g_bq_p2[j];
        // dot via fma chain (cublas-style), then d2 = (s1+s2) - 2*dot
        float dot = fmaf(z1, q.z, fmaf(y1, q.y, __fmul_rn(x1, q.x)));
        float d2 = __fsub_rn(__fadd_rn(s1, q.w), __fmul_rn(2.0f, dot));
        bool hit = (d2 <= BQ_R2);
        unsigned mask = __ballot_sync(0xffffffffu, hit);
        if (mask) {
            int rank = cnt + __popc(mask & lanes_below);
            if (hit && rank < BQ_K) {
                mapping[rank] = (float)j;
                coords[rank * 3 + 0] = q.x;
                coords[rank * 3 + 1] = q.y;
                coords[rank * 3 + 2] = q.z;
            }
            cnt += __popc(mask);
            if (cnt >= BQ_K) break;
        }
    }

    int n = cnt < BQ_K ? cnt : BQ_K;
    if (lane == 0) *num_out = (float)n;
    // zero-pad remaining slots (d_out is poisoned 0xAA by the harness)
    for (int s = n + lane; s < BQ_K; s += 32) {
        mapping[s] = 0.0f;
        coords[s * 3 + 0] = 0.0f;
        coords[s * 3 + 1] = 0.0f;
        coords[s * 3 + 2] = 0.0f;
    }
}

extern "C" void kernel_launch(void* const* d_in, const int* in_sizes, int n_in,
                              void* d_out, int out_size) {
    const float* p1 = (const float*)d_in[0];
    const float* p2 = (const float*)d_in[1];
    float* out = (float*)d_out;

    bq_pack_p2<<<(BQ_N2 + 255) / 256, 256>>>(p2);
    // 4096 warps = one per query; 256 threads/block -> 512 blocks
    bq_query<<<(BQ_N1 * 32 + 255) / 256, 256>>>(p1, out);
}

// round 2
// speedup vs baseline: 5.8736x; 5.8736x over previous
#include <cuda_runtime.h>

// Ball query via uniform spatial grid.
// N1=4096 queries, N2=16384 refs, K=32, radius=0.08, points uniform in [0,1)^3.
// Grid: 12^3 cells, edge 1/12 = 0.0833 >= radius, so 3x3x3 neighborhood covers
// the ball. Counting-sort p2 into cell order, per-query warp scans ~256
// candidates (vs 16384 brute force), collects ALL hits (expected ~35, buffer
// 128), then ranks by original index to reproduce the reference's
// "first K in ascending index order" semantics exactly.
//
// Hit predicate is bit-identical to the verified Round-1 formula:
//   s = ((x*x + y*y) + z*z)  (mul/add, no fma)
//   dot = fmaf(z1,z2, fmaf(y1,y2, x1*x2))
//   d2  = (s1 + s2) - 2*dot;  hit iff d2 <= r^2

#define BQ_N1 4096
#define BQ_N2 16384
#define BQ_K 32
#define BQ_R2 0.0064f
#define BQ_G 12
#define BQ_NC (BQ_G * BQ_G * BQ_G)   // 1728
#define BQ_BUF 128                   // per-warp hit buffer (P(hits>128) ~ 0)

__device__ int    g_cell_count[BQ_NC];
__device__ int    g_cell_start[BQ_NC + 1];
__device__ int    g_cell_cursor[BQ_NC];
__device__ float4 g_pts[BQ_N2];      // x, y, z, |p|^2  (cell-sorted)
__device__ int    g_idx[BQ_N2];      // original index  (cell-sorted)

__device__ __forceinline__ int bq_cell1(float v) {
    int c = (int)(v * (float)BQ_G);
    return c < 0 ? 0 : (c > BQ_G - 1 ? BQ_G - 1 : c);
}

__global__ void bq_zero() {
    int i = blockIdx.x * blockDim.x + threadIdx.x;
    if (i < BQ_NC) g_cell_count[i] = 0;
}

__global__ void bq_count(const float* __restrict__ p2) {
    int j = blockIdx.x * blockDim.x + threadIdx.x;
    if (j < BQ_N2) {
        int cx = bq_cell1(p2[3 * j + 0]);
        int cy = bq_cell1(p2[3 * j + 1]);
        int cz = bq_cell1(p2[3 * j + 2]);
        atomicAdd(&g_cell_count[(cz * BQ_G + cy) * BQ_G + cx], 1);
    }
}

// Single-block exclusive scan over 1728 counts (2 elements per thread).
__global__ __launch_bounds__(1024) void bq_scan() {
    __shared__ int sh[1024];
    int t = threadIdx.x;
    int i0 = 2 * t, i1 = 2 * t + 1;
    int a = (i0 < BQ_NC) ? g_cell_count[i0] : 0;
    int b = (i1 < BQ_NC) ? g_cell_count[i1] : 0;
    sh[t] = a + b;
    __syncthreads();
    for (int off = 1; off < 1024; off <<= 1) {
        int add = (t >= off) ? sh[t - off] : 0;
        __syncthreads();
        sh[t] += add;
        __syncthreads();
    }
    int excl = sh[t] - (a + b);  // exclusive prefix of this pair
    if (i0 < BQ_NC) { g_cell_start[i0] = excl;     g_cell_cursor[i0] = excl; }
    if (i1 < BQ_NC) { g_cell_start[i1] = excl + a; g_cell_cursor[i1] = excl + a; }
    if (t == 1023) g_cell_start[BQ_NC] = sh[1023];
}

__global__ void bq_scatter(const float* __restrict__ p2) {
    int j = blockIdx.x * blockDim.x + threadIdx.x;
    if (j < BQ_N2) {
        float x = p2[3 * j + 0];
        float y = p2[3 * j + 1];
        float z = p2[3 * j + 2];
        int cx = bq_cell1(x), cy = bq_cell1(y), cz = bq_cell1(z);
        int c = (cz * BQ_G + cy) * BQ_G + cx;
        int pos = atomicAdd(&g_cell_cursor[c], 1);
        float s2 = __fadd_rn(__fadd_rn(__fmul_rn(x, x), __fmul_rn(y, y)),
                             __fmul_rn(z, z));
        g_pts[pos] = make_float4(x, y, z, s2);
        g_idx[pos] = j;
    }
}

__global__ __launch_bounds__(256) void bq_query(const float* __restrict__ p1,
                                                float* __restrict__ out) {
    __shared__ int sh_hits[8][BQ_BUF];
    int warp = threadIdx.x >> 5;
    int lane = threadIdx.x & 31;
    int q = (blockIdx.x * blockDim.x + threadIdx.x) >> 5;
    if (q >= BQ_N1) return;
    int* buf = sh_hits[warp];

    float x1 = p1[3 * q + 0];
    float y1 = p1[3 * q + 1];
    float z1 = p1[3 * q + 2];
    float s1 = __fadd_rn(__fadd_rn(__fmul_rn(x1, x1), __fmul_rn(y1, y1)),
                         __fmul_rn(z1, z1));

    int cx = bq_cell1(x1), cy = bq_cell1(y1), cz = bq_cell1(z1);
    int xlo = cx > 0 ? cx - 1 : 0;
    int xhi = cx < BQ_G - 1 ? cx + 1 : BQ_G - 1;

    unsigned below = (1u << lane) - 1u;
    int cnt = 0;

    #pragma unroll 1
    for (int dz = -1; dz <= 1; dz++) {
        int zz = cz + dz;
        if (zz < 0 || zz >= BQ_G) continue;
        #pragma unroll 1
        for (int dy = -1; dy <= 1; dy++) {
            int yy = cy + dy;
            if (yy < 0 || yy >= BQ_G) continue;
            int rowbase = (zz * BQ_G + yy) * BQ_G;
            int s = g_cell_start[rowbase + xlo];
            int e = g_cell_start[rowbase + xhi + 1];
            for (int base = s; base < e; base += 32) {
                int t = base + lane;
                bool hit = false;
                int key = 0;
                if (t < e) {
                    float4 p = g_pts[t];
                    float dot = fmaf(z1, p.z, fmaf(y1, p.y, __fmul_rn(x1, p.x)));
                    float d2 = __fsub_rn(__fadd_rn(s1, p.w),
                                         __fmul_rn(2.0f, dot));
                    if (d2 <= BQ_R2) {
                        hit = true;
                        key = (g_idx[t] << 14) | t;
                    }
                }
                unsigned mask = __ballot_sync(0xffffffffu, hit);
                if (hit) {
                    int pos = cnt + __popc(mask & below);
                    if (pos < BQ_BUF) buf[pos] = key;
                }
                cnt += __popc(mask);
            }
        }
    }
    __syncwarp();

    float* mapping = out + (size_t)q * BQ_K;
    float* num_out = out + (size_t)BQ_N1 * BQ_K + q;
    float* coords  = out + (size_t)BQ_N1 * BQ_K + BQ_N1 + (size_t)q * BQ_K * 3;

    int cc = cnt < BQ_BUF ? cnt : BQ_BUF;
    // Rank each hit by key (== by original index; keys unique); rank<K -> slot.
    for (int e0 = lane; e0 < cc; e0 += 32) {
        int key = buf[e0];
        int rank = 0;
        for (int i = 0; i < cc; i++) rank += (buf[i] < key);
        if (rank < BQ_K) {
            int t = key & 0x3FFF;
            float4 p = g_pts[t];
            mapping[rank] = (float)(key >> 14);
            coords[rank * 3 + 0] = p.x;
            coords[rank * 3 + 1] = p.y;
            coords[rank * 3 + 2] = p.z;
        }
    }

    int n = cnt < BQ_K ? cnt : BQ_K;
    if (lane == 0) *num_out = (float)n;
    for (int s = n + lane; s < BQ_K; s += 32) {
        mapping[s] = 0.0f;
        coords[s * 3 + 0] = 0.0f;
        coords[s * 3 + 1] = 0.0f;
        coords[s * 3 + 2] = 0.0f;
    }
}

extern "C" void kernel_launch(void* const* d_in, const int* in_sizes, int n_in,
                              void* d_out, int out_size) {
    const float* p1 = (const float*)d_in[0];
    const float* p2 = (const float*)d_in[1];
    float* out = (float*)d_out;

    bq_zero<<<(BQ_NC + 255) / 256, 256>>>();
    bq_count<<<(BQ_N2 + 255) / 256, 256>>>(p2);
    bq_scan<<<1, 1024>>>();
    bq_scatter<<<(BQ_N2 + 255) / 256, 256>>>(p2);
    bq_query<<<(BQ_N1 * 32 + 255) / 256, 256>>>(p1, out);
}